// round 4
// baseline (speedup 1.0000x reference)
#include <cuda_runtime.h>

#define BB 4
#define CC 256
#define HH 256
#define WW 256
#define RR 64
#define HL 64
#define WL 64
#define LRN (HL*WL)      // 4096
#define PLN (HH*WW)      // 65536

// Scratch (no allocation allowed -> device globals).
__device__ float g_fgp[4][BB*RR*LRN];   // 4 channel-group partials of fg
__device__ float g_ftp[4][BB*RR*LRN];   // 4 channel-group partials of ft
__device__ float g_a [BB*RR*LRN];
__device__ float g_bv[BB*RR*LRN];
__device__ float g_A [BB*CC*LRN];
__device__ float g_B [BB*CC*LRN];
__device__ float g_wrg_t[CC*RR];  // [c][r]
__device__ float g_wrt_t[CC*RR];  // [c][r]
__device__ float g_wua_t[RR*CC];  // [r][o]
__device__ float g_wub_t[RR*CC];  // [r][o]

typedef unsigned long long u64;

__device__ __forceinline__ u64 pack2(float lo, float hi) {
    u64 r; asm("mov.b64 %0, {%1, %2};" : "=l"(r) : "f"(lo), "f"(hi)); return r;
}
__device__ __forceinline__ void fma2(u64& d, u64 a, u64 b) {
    asm("fma.rn.f32x2 %0, %1, %2, %0;" : "+l"(d) : "l"(a), "l"(b));
}
__device__ __forceinline__ float2 unpk(u64 v) {
    float2 f; asm("mov.b64 {%0, %1}, %2;" : "=f"(f.x), "=f"(f.y) : "l"(v)); return f;
}

// K0: transpose weights into GEMM-friendly layouts.
__global__ void k_prep(const float* __restrict__ wrg, const float* __restrict__ wrt,
                       const float* __restrict__ wua, const float* __restrict__ wub) {
    int i = blockIdx.x * 256 + threadIdx.x;   // 16384 total
    if (i < CC*RR) {
        int c = i >> 6, r = i & 63;           // i = c*64 + r
        g_wrg_t[i] = wrg[r*CC + c];
        g_wrt_t[i] = wrt[r*CC + c];
        int rr = i >> 8, o = i & 255;         // i = rr*256 + o
        g_wua_t[i] = wua[o*RR + rr];
        g_wub_t[i] = wub[o*RR + rr];
    }
}

// K12 (fused): bilinear downsample 256->64 + partial C->R projection over a
// 64-channel group, staged-GEMM style.
// Phase A (per 16-c chunk): each thread computes ds for its own pixel, 16 c.
// Phase B: register tile px4 x r16 per thread; ds + weights from smem.
// grid: (64 px-blocks, 4 c-groups, 2 tensors), 256 threads.
__global__ __launch_bounds__(256) void k_ds_proj(const float* __restrict__ enc,
                                                 const float* __restrict__ dec) {
    __shared__ float w_sm[64*RR];      // 16KB: [c_local][r]
    __shared__ float ds_sm[16*256];    // 16KB: [c_chunk_local][px_local]
    int cg = blockIdx.y;
    const float* in  = (blockIdx.z == 0) ? enc     : dec;
    const float* wt  = (blockIdx.z == 0) ? g_wrg_t : g_wrt_t;
    float*       out = (blockIdx.z == 0) ? &g_fgp[cg][0] : &g_ftp[cg][0];
    int t = threadIdx.x;
    for (int i = t; i < 64*RR; i += 256)
        w_sm[i] = wt[(cg*64 + (i >> 6))*RR + (i & 63)];

    int q = blockIdx.x * 256 + t;           // this thread's staging pixel
    int b = q >> 12, rest = q & 4095;
    int x = rest & 63, y = rest >> 6;
    const float* base = in + (size_t)b * CC * PLN + (size_t)cg * 64 * PLN
                           + (size_t)(4*y + 1) * WW + 4*x;

    int rg = t & 3, pg = t >> 2;            // GEMM role: 16 r's, 4 px's

    u64 acc[4][8];
    #pragma unroll
    for (int p = 0; p < 4; p++)
        #pragma unroll
        for (int j = 0; j < 8; j++) acc[p][j] = 0ull;

    for (int ch = 0; ch < 4; ch++) {        // 4 chunks of 16 channels
        __syncthreads();
        #pragma unroll 4
        for (int cl = 0; cl < 16; cl++) {
            const float* p = base + (size_t)(ch*16 + cl) * PLN;
            float4 r0 = *(const float4*)p;
            float4 r1 = *(const float4*)(p + WW);
            ds_sm[cl*256 + t] = 0.25f * ((r0.y + r0.z) + (r1.y + r1.z));
        }
        __syncthreads();
        #pragma unroll 4
        for (int cl = 0; cl < 16; cl++) {
            int c = ch*16 + cl;
            float4 d = *(const float4*)(ds_sm + cl*256 + pg*4);
            u64 d2[4];
            d2[0] = pack2(d.x, d.x); d2[1] = pack2(d.y, d.y);
            d2[2] = pack2(d.z, d.z); d2[3] = pack2(d.w, d.w);
            const ulonglong2* wp = (const ulonglong2*)(w_sm + c*RR + rg*16);
            #pragma unroll
            for (int jj = 0; jj < 4; jj++) {
                ulonglong2 wv = wp[jj];
                #pragma unroll
                for (int p = 0; p < 4; p++) {
                    fma2(acc[p][2*jj    ], wv.x, d2[p]);
                    fma2(acc[p][2*jj + 1], wv.y, d2[p]);
                }
            }
        }
    }
    // Write px4-coalesced: for each of 16 r's, a float4 across the 4 pixels.
    int rest0 = (blockIdx.x * 256 + pg*4) & 4095;
    float* pout = out + (size_t)b * RR * LRN + rest0 + (size_t)(rg*16) * LRN;
    #pragma unroll
    for (int k = 0; k < 8; k++) {
        float2 u0 = unpk(acc[0][k]), u1 = unpk(acc[1][k]);
        float2 u2 = unpk(acc[2][k]), u3 = unpk(acc[3][k]);
        *(float4*)(pout + (size_t)(2*k    ) * LRN) = make_float4(u0.x, u1.x, u2.x, u3.x);
        *(float4*)(pout + (size_t)(2*k + 1) * LRN) = make_float4(u0.y, u1.y, u2.y, u3.y);
    }
}

// K3a: sum 4 channel-group partials, 3x3 zero-padded box mean (/9) + a,b.
__global__ __launch_bounds__(256) void k_guided(const float* __restrict__ eps_p) {
    __shared__ float gs[LRN], ts[LRN];
    int pl = blockIdx.x;  // b*RR + r
    size_t off = (size_t)pl * LRN;
    int t = threadIdx.x;
    for (int i = t; i < LRN; i += 256) {
        gs[i] = (g_fgp[0][off+i] + g_fgp[1][off+i]) + (g_fgp[2][off+i] + g_fgp[3][off+i]);
        ts[i] = (g_ftp[0][off+i] + g_ftp[1][off+i]) + (g_ftp[2][off+i] + g_ftp[3][off+i]);
    }
    __syncthreads();
    float eps = *eps_p;
    const float inv9 = 1.0f / 9.0f;
    for (int i = t; i < LRN; i += 256) {
        int y = i >> 6, x = i & 63;
        float sg = 0.f, st = 0.f, sgg = 0.f, sgt = 0.f;
        #pragma unroll
        for (int dy = -1; dy <= 1; dy++) {
            int yy = y + dy;
            if (yy < 0 || yy > 63) continue;
            #pragma unroll
            for (int dx = -1; dx <= 1; dx++) {
                int xx = x + dx;
                if (xx < 0 || xx > 63) continue;
                float g = gs[yy*64 + xx], v = ts[yy*64 + xx];
                sg += g; st += v; sgg += g*g; sgt += g*v;
            }
        }
        float mg  = sg  * inv9, mt = st * inv9;
        float var = sgg * inv9 - mg*mg;
        float cov = sgt * inv9 - mg*mt;
        float a  = cov / (var + eps);
        float bv = mt - a * mg;
        g_a [off + i] = a;
        g_bv[off + i] = bv;
    }
}

// K3b: R=64 -> C=256 projection at low-res. px-tile=2, o-tile=8 (low regs, high occ).
// grid: (32 px-blocks, 32 o-blocks). Per r: 2 LDG.64 + 4 LDS.128 + 16 fma2.
__global__ __launch_bounds__(256) void k_proj_rc() {
    __shared__ float wa_sm[RR*8], wb_sm[RR*8];
    int o0 = blockIdx.y * 8;
    int t = threadIdx.x;
    for (int i = t; i < RR*8; i += 256) {
        int r = i >> 3, j = i & 7;
        wa_sm[i] = g_wua_t[r*CC + o0 + j];
        wb_sm[i] = g_wub_t[r*CC + o0 + j];
    }
    __syncthreads();
    int q = (blockIdx.x * 256 + t) * 2;     // 2 consecutive pixels
    int b = q >> 12, rest = q & 4095;
    const float* pa = g_a  + (size_t)b * RR * LRN + rest;
    const float* pb = g_bv + (size_t)b * RR * LRN + rest;
    u64 accA0[4], accA1[4], accB0[4], accB1[4];
    #pragma unroll
    for (int j = 0; j < 4; j++) { accA0[j]=0ull; accA1[j]=0ull; accB0[j]=0ull; accB1[j]=0ull; }
    #pragma unroll 4
    for (int r = 0; r < RR; r++) {
        float2 av = *(const float2*)(pa + (size_t)r * LRN);
        float2 bv = *(const float2*)(pb + (size_t)r * LRN);
        u64 a0 = pack2(av.x, av.x), a1 = pack2(av.y, av.y);
        u64 b0 = pack2(bv.x, bv.x), b1 = pack2(bv.y, bv.y);
        const ulonglong2* wap = (const ulonglong2*)(wa_sm + r*8);
        const ulonglong2* wbp = (const ulonglong2*)(wb_sm + r*8);
        #pragma unroll
        for (int j = 0; j < 2; j++) {
            ulonglong2 wa = wap[j];
            fma2(accA0[2*j  ], wa.x, a0); fma2(accA1[2*j  ], wa.x, a1);
            fma2(accA0[2*j+1], wa.y, a0); fma2(accA1[2*j+1], wa.y, a1);
            ulonglong2 wb = wbp[j];
            fma2(accB0[2*j  ], wb.x, b0); fma2(accB1[2*j  ], wb.x, b1);
            fma2(accB0[2*j+1], wb.y, b0); fma2(accB1[2*j+1], wb.y, b1);
        }
    }
    float* oA = g_A + (size_t)b * CC * LRN + rest;
    float* oB = g_B + (size_t)b * CC * LRN + rest;
    #pragma unroll
    for (int j = 0; j < 4; j++) {
        float2 va0 = unpk(accA0[j]), va1 = unpk(accA1[j]);
        float2 vb0 = unpk(accB0[j]), vb1 = unpk(accB1[j]);
        *(float2*)(oA + (size_t)(o0 + 2*j    ) * LRN) = make_float2(va0.x, va1.x);
        *(float2*)(oA + (size_t)(o0 + 2*j + 1) * LRN) = make_float2(va0.y, va1.y);
        *(float2*)(oB + (size_t)(o0 + 2*j    ) * LRN) = make_float2(vb0.x, vb1.x);
        *(float2*)(oB + (size_t)(o0 + 2*j + 1) * LRN) = make_float2(vb0.y, vb1.y);
    }
}

// K4: fused bilinear 64->256 upsample of A,B + out = F_dec + A*F_enc + B.
// One block per (b,c) plane: A,B low-res planes loaded into smem ONCE.
__global__ __launch_bounds__(256) void k_fuse(const float* __restrict__ enc,
                                              const float* __restrict__ dec,
                                              float* __restrict__ out) {
    __shared__ float As[LRN], Bs[LRN];
    int plane = blockIdx.x;
    const float* Ap = g_A + (size_t)plane * LRN;
    const float* Bp = g_B + (size_t)plane * LRN;
    int t = threadIdx.x;
    for (int i = t; i < LRN; i += 256) { As[i] = Ap[i]; Bs[i] = Bp[i]; }
    __syncthreads();
    const float* ep = enc + (size_t)plane * PLN;
    const float* dp = dec + (size_t)plane * PLN;
    float*       op = out + (size_t)plane * PLN;
    int xg = t & 63, ys = t >> 6;
    int cm = max(xg - 1, 0), cp = min(xg + 1, 63);
    for (int yy = 0; yy < 64; yy++) {
        int y = yy*4 + ys;
        float sy = fmaxf((float)y * 0.25f - 0.375f, 0.0f);
        int y0 = (int)sy;
        float wy = sy - (float)y0;
        int y1 = min(y0 + 1, 63);
        const float* rA0 = As + y0*64; const float* rA1 = As + y1*64;
        const float* rB0 = Bs + y0*64; const float* rB1 = Bs + y1*64;
        float am = rA0[cm] + wy * (rA1[cm] - rA0[cm]);
        float ac = rA0[xg] + wy * (rA1[xg] - rA0[xg]);
        float ap = rA0[cp] + wy * (rA1[cp] - rA0[cp]);
        float bm = rB0[cm] + wy * (rB1[cm] - rB0[cm]);
        float bc = rB0[xg] + wy * (rB1[xg] - rB0[xg]);
        float bp = rB0[cp] + wy * (rB1[cp] - rB0[cp]);
        float A0, A1, B0v, B1v;
        if (xg == 0) { A0 = ac; A1 = ac; B0v = bc; B1v = bc; }  // src clamped to 0, w=0
        else {
            A0  = am + 0.625f * (ac - am);
            A1  = am + 0.875f * (ac - am);
            B0v = bm + 0.625f * (bc - bm);
            B1v = bm + 0.875f * (bc - bm);
        }
        float A2 = ac + 0.125f * (ap - ac), A3 = ac + 0.375f * (ap - ac);
        float B2 = bc + 0.125f * (bp - bc), B3 = bc + 0.375f * (bp - bc);
        size_t off = (size_t)y * WW + xg * 4;
        float4 e = *(const float4*)(ep + off);
        float4 d = *(const float4*)(dp + off);
        float4 o;
        o.x = d.x + A0 * e.x + B0v;
        o.y = d.y + A1 * e.y + B1v;
        o.z = d.z + A2 * e.z + B2;
        o.w = d.w + A3 * e.w + B3;
        *(float4*)(op + off) = o;
    }
}

extern "C" void kernel_launch(void* const* d_in, const int* in_sizes, int n_in,
                              void* d_out, int out_size) {
    const float* F_enc = (const float*)d_in[0];
    const float* F_dec = (const float*)d_in[1];
    const float* w_rg  = (const float*)d_in[2];
    const float* w_rt  = (const float*)d_in[3];
    const float* w_ua  = (const float*)d_in[4];
    const float* w_ub  = (const float*)d_in[5];
    const float* eps   = (const float*)d_in[6];
    float* out = (float*)d_out;

    k_prep<<<64, 256>>>(w_rg, w_rt, w_ua, w_ub);
    k_ds_proj<<<dim3(64, 4, 2), 256>>>(F_enc, F_dec);
    k_guided<<<BB*RR, 256>>>(eps);
    k_proj_rc<<<dim3(32, 32), 256>>>();
    k_fuse<<<BB*CC, 256>>>(F_enc, F_dec, out);
}

// round 6
// speedup vs baseline: 1.2827x; 1.2827x over previous
#include <cuda_runtime.h>

#define BB 4
#define CC 256
#define HH 256
#define WW 256
#define RR 64
#define HL 64
#define WL 64
#define LRN (HL*WL)      // 4096
#define PLN (HH*WW)      // 65536

// Scratch (no allocation allowed -> device globals).
__device__ float g_fgp[2][BB*RR*LRN];   // 2 channel-group partials of fg
__device__ float g_ftp[2][BB*RR*LRN];   // 2 channel-group partials of ft
__device__ float g_a [BB*RR*LRN];
__device__ float g_bv[BB*RR*LRN];
__device__ float g_A [BB*CC*LRN];
__device__ float g_B [BB*CC*LRN];
__device__ float g_wrg_t[CC*RR];  // [c][r]
__device__ float g_wrt_t[CC*RR];  // [c][r]
__device__ float g_wua_t[RR*CC];  // [r][o]
__device__ float g_wub_t[RR*CC];  // [r][o]

typedef unsigned long long u64;

__device__ __forceinline__ u64 pack2(float lo, float hi) {
    u64 r; asm("mov.b64 %0, {%1, %2};" : "=l"(r) : "f"(lo), "f"(hi)); return r;
}
__device__ __forceinline__ void fma2(u64& d, u64 a, u64 b) {
    asm("fma.rn.f32x2 %0, %1, %2, %0;" : "+l"(d) : "l"(a), "l"(b));
}
__device__ __forceinline__ float2 unpk(u64 v) {
    float2 f; asm("mov.b64 {%0, %1}, %2;" : "=f"(f.x), "=f"(f.y) : "l"(v)); return f;
}

// K0: transpose weights into GEMM-friendly layouts.
__global__ void k_prep(const float* __restrict__ wrg, const float* __restrict__ wrt,
                       const float* __restrict__ wua, const float* __restrict__ wub) {
    int i = blockIdx.x * 256 + threadIdx.x;   // 16384 total
    if (i < CC*RR) {
        int c = i >> 6, r = i & 63;           // i = c*64 + r
        g_wrg_t[i] = wrg[r*CC + c];
        g_wrt_t[i] = wrt[r*CC + c];
        int rr = i >> 8, o = i & 255;         // i = rr*256 + o
        g_wua_t[i] = wua[o*RR + rr];
        g_wub_t[i] = wub[o*RR + rr];
    }
}

// K12 (fused): bilinear downsample 256->64 + partial C->R projection over a
// 128-channel group, staged GEMM with double-buffered ds tiles.
// Per 8-channel chunk: fill ds buffer (own pixel), 1 sync, GEMM phase
// (1 LDS.128 ds + 4 broadcast LDS.128 weights per 32 fma2 -> FMA-bound).
// grid: (64 px-blocks, 2 c-groups, 2 tensors), 256 threads.
__global__ __launch_bounds__(256) void k_ds_proj(const float* __restrict__ enc,
                                                 const float* __restrict__ dec) {
    __shared__ float w_sm[128*RR];       // 32KB: [c_local][r]
    __shared__ float ds_sm[2][8*256];    // 2 x 8KB: [c_chunk_local][px_local]
    int cg = blockIdx.y;
    const float* in  = (blockIdx.z == 0) ? enc     : dec;
    const float* wt  = (blockIdx.z == 0) ? g_wrg_t : g_wrt_t;
    float*       out = (blockIdx.z == 0) ? &g_fgp[cg][0] : &g_ftp[cg][0];
    int t = threadIdx.x;
    for (int i = t; i < 128*RR; i += 256)
        w_sm[i] = wt[(cg*128 + (i >> 6))*RR + (i & 63)];

    int q = blockIdx.x * 256 + t;           // this thread's staging pixel
    int b = q >> 12, rest = q & 4095;
    int x = rest & 63, y = rest >> 6;
    const float* base = in + (size_t)b * CC * PLN + (size_t)cg * 128 * PLN
                           + (size_t)(4*y + 1) * WW + 4*x;

    int rg = t & 3, pg = t >> 2;            // GEMM role: 16 r's, 4 px's

    u64 acc[4][8];
    #pragma unroll
    for (int p = 0; p < 4; p++)
        #pragma unroll
        for (int j = 0; j < 8; j++) acc[p][j] = 0ull;

    for (int ch = 0; ch < 16; ch++) {       // 16 chunks of 8 channels
        int buf = ch & 1;
        // Fill phase: this thread's pixel, 8 channels (16 LDG.128, MLP-friendly).
        #pragma unroll
        for (int cl = 0; cl < 8; cl++) {
            const float* p = base + (size_t)(ch*8 + cl) * PLN;
            float4 r0 = *(const float4*)p;
            float4 r1 = *(const float4*)(p + WW);
            ds_sm[buf][cl*256 + t] = 0.25f * ((r0.y + r0.z) + (r1.y + r1.z));
        }
        __syncthreads();
        // GEMM phase on this buffer. Next iteration fills the other buffer,
        // so its LDGs overlap this compute; buffer reuse is protected by the
        // sync of the following iteration.
        #pragma unroll
        for (int cl = 0; cl < 8; cl++) {
            int c = ch*8 + cl;
            float4 d = *(const float4*)(ds_sm[buf] + cl*256 + pg*4);
            u64 d2[4];
            d2[0] = pack2(d.x, d.x); d2[1] = pack2(d.y, d.y);
            d2[2] = pack2(d.z, d.z); d2[3] = pack2(d.w, d.w);
            const ulonglong2* wp = (const ulonglong2*)(w_sm + c*RR + rg*16);
            #pragma unroll
            for (int jj = 0; jj < 4; jj++) {
                ulonglong2 wv = wp[jj];
                #pragma unroll
                for (int p = 0; p < 4; p++) {
                    fma2(acc[p][2*jj    ], wv.x, d2[p]);
                    fma2(acc[p][2*jj + 1], wv.y, d2[p]);
                }
            }
        }
    }
    // Write px4-coalesced: for each of 16 r's, a float4 across the 4 pixels.
    int rest0 = (blockIdx.x * 256 + pg*4) & 4095;
    float* pout = out + (size_t)b * RR * LRN + rest0 + (size_t)(rg*16) * LRN;
    #pragma unroll
    for (int k = 0; k < 8; k++) {
        float2 u0 = unpk(acc[0][k]), u1 = unpk(acc[1][k]);
        float2 u2 = unpk(acc[2][k]), u3 = unpk(acc[3][k]);
        *(float4*)(pout + (size_t)(2*k    ) * LRN) = make_float4(u0.x, u1.x, u2.x, u3.x);
        *(float4*)(pout + (size_t)(2*k + 1) * LRN) = make_float4(u0.y, u1.y, u2.y, u3.y);
    }
}

// K3a: sum 2 channel-group partials, 3x3 zero-padded box mean (/9) + a,b.
__global__ __launch_bounds__(256) void k_guided(const float* __restrict__ eps_p) {
    __shared__ float gs[LRN], ts[LRN];
    int pl = blockIdx.x;  // b*RR + r
    size_t off = (size_t)pl * LRN;
    int t = threadIdx.x;
    for (int i = t; i < LRN; i += 256) {
        gs[i] = g_fgp[0][off+i] + g_fgp[1][off+i];
        ts[i] = g_ftp[0][off+i] + g_ftp[1][off+i];
    }
    __syncthreads();
    float eps = *eps_p;
    const float inv9 = 1.0f / 9.0f;
    for (int i = t; i < LRN; i += 256) {
        int y = i >> 6, x = i & 63;
        float sg = 0.f, st = 0.f, sgg = 0.f, sgt = 0.f;
        #pragma unroll
        for (int dy = -1; dy <= 1; dy++) {
            int yy = y + dy;
            if (yy < 0 || yy > 63) continue;
            #pragma unroll
            for (int dx = -1; dx <= 1; dx++) {
                int xx = x + dx;
                if (xx < 0 || xx > 63) continue;
                float g = gs[yy*64 + xx], v = ts[yy*64 + xx];
                sg += g; st += v; sgg += g*g; sgt += g*v;
            }
        }
        float mg  = sg  * inv9, mt = st * inv9;
        float var = sgg * inv9 - mg*mg;
        float cov = sgt * inv9 - mg*mt;
        float a  = cov / (var + eps);
        float bv = mt - a * mg;
        g_a [off + i] = a;
        g_bv[off + i] = bv;
    }
}

// K3b: R=64 -> C=256 projection at low-res. px-tile=2 (float2), o-tile=16.
// grid: (32 px-blocks, 16 o-blocks). (Proven R3 config: 42.8us.)
__global__ __launch_bounds__(256) void k_proj_rc() {
    __shared__ float wa_sm[RR*16], wb_sm[RR*16];
    int o0 = blockIdx.y * 16;
    int t = threadIdx.x;
    for (int i = t; i < RR*16; i += 256) {
        int r = i >> 4, j = i & 15;
        wa_sm[i] = g_wua_t[r*CC + o0 + j];
        wb_sm[i] = g_wub_t[r*CC + o0 + j];
    }
    __syncthreads();
    int q = (blockIdx.x * 256 + t) * 2;     // 2 consecutive pixels
    int b = q >> 12, rest = q & 4095;
    const float* pa = g_a  + (size_t)b * RR * LRN + rest;
    const float* pb = g_bv + (size_t)b * RR * LRN + rest;
    u64 accA0[8], accA1[8], accB0[8], accB1[8];
    #pragma unroll
    for (int j = 0; j < 8; j++) { accA0[j]=0ull; accA1[j]=0ull; accB0[j]=0ull; accB1[j]=0ull; }
    #pragma unroll 2
    for (int r = 0; r < RR; r++) {
        float2 av = *(const float2*)(pa + (size_t)r * LRN);
        float2 bv = *(const float2*)(pb + (size_t)r * LRN);
        u64 a0 = pack2(av.x, av.x), a1 = pack2(av.y, av.y);
        u64 b0 = pack2(bv.x, bv.x), b1 = pack2(bv.y, bv.y);
        const ulonglong2* wap = (const ulonglong2*)(wa_sm + r*16);
        const ulonglong2* wbp = (const ulonglong2*)(wb_sm + r*16);
        #pragma unroll
        for (int j = 0; j < 4; j++) {
            ulonglong2 wa = wap[j];
            fma2(accA0[2*j  ], wa.x, a0); fma2(accA1[2*j  ], wa.x, a1);
            fma2(accA0[2*j+1], wa.y, a0); fma2(accA1[2*j+1], wa.y, a1);
            ulonglong2 wb = wbp[j];
            fma2(accB0[2*j  ], wb.x, b0); fma2(accB1[2*j  ], wb.x, b1);
            fma2(accB0[2*j+1], wb.y, b0); fma2(accB1[2*j+1], wb.y, b1);
        }
    }
    float* oA = g_A + (size_t)b * CC * LRN + rest;
    float* oB = g_B + (size_t)b * CC * LRN + rest;
    #pragma unroll
    for (int j = 0; j < 8; j++) {
        float2 va0 = unpk(accA0[j]), va1 = unpk(accA1[j]);
        float2 vb0 = unpk(accB0[j]), vb1 = unpk(accB1[j]);
        *(float2*)(oA + (size_t)(o0 + 2*j    ) * LRN) = make_float2(va0.x, va1.x);
        *(float2*)(oA + (size_t)(o0 + 2*j + 1) * LRN) = make_float2(va0.y, va1.y);
        *(float2*)(oB + (size_t)(o0 + 2*j    ) * LRN) = make_float2(vb0.x, vb1.x);
        *(float2*)(oB + (size_t)(o0 + 2*j + 1) * LRN) = make_float2(vb0.y, vb1.y);
    }
}

// K4: fused bilinear 64->256 upsample of A,B + out = F_dec + A*F_enc + B.
// One block per (b,c) plane: A,B low-res planes loaded into smem ONCE.
__global__ __launch_bounds__(256) void k_fuse(const float* __restrict__ enc,
                                              const float* __restrict__ dec,
                                              float* __restrict__ out) {
    __shared__ float As[LRN], Bs[LRN];
    int plane = blockIdx.x;
    const float* Ap = g_A + (size_t)plane * LRN;
    const float* Bp = g_B + (size_t)plane * LRN;
    int t = threadIdx.x;
    for (int i = t; i < LRN; i += 256) { As[i] = Ap[i]; Bs[i] = Bp[i]; }
    __syncthreads();
    const float* ep = enc + (size_t)plane * PLN;
    const float* dp = dec + (size_t)plane * PLN;
    float*       op = out + (size_t)plane * PLN;
    int xg = t & 63, ys = t >> 6;
    int cm = max(xg - 1, 0), cp = min(xg + 1, 63);
    for (int yy = 0; yy < 64; yy++) {
        int y = yy*4 + ys;
        float sy = fmaxf((float)y * 0.25f - 0.375f, 0.0f);
        int y0 = (int)sy;
        float wy = sy - (float)y0;
        int y1 = min(y0 + 1, 63);
        const float* rA0 = As + y0*64; const float* rA1 = As + y1*64;
        const float* rB0 = Bs + y0*64; const float* rB1 = Bs + y1*64;
        float am = rA0[cm] + wy * (rA1[cm] - rA0[cm]);
        float ac = rA0[xg] + wy * (rA1[xg] - rA0[xg]);
        float ap = rA0[cp] + wy * (rA1[cp] - rA0[cp]);
        float bm = rB0[cm] + wy * (rB1[cm] - rB0[cm]);
        float bc = rB0[xg] + wy * (rB1[xg] - rB0[xg]);
        float bp = rB0[cp] + wy * (rB1[cp] - rB0[cp]);
        float A0, A1, B0v, B1v;
        if (xg == 0) { A0 = ac; A1 = ac; B0v = bc; B1v = bc; }  // src clamped to 0, w=0
        else {
            A0  = am + 0.625f * (ac - am);
            A1  = am + 0.875f * (ac - am);
            B0v = bm + 0.625f * (bc - bm);
            B1v = bm + 0.875f * (bc - bm);
        }
        float A2 = ac + 0.125f * (ap - ac), A3 = ac + 0.375f * (ap - ac);
        float B2 = bc + 0.125f * (bp - bc), B3 = bc + 0.375f * (bp - bc);
        size_t off = (size_t)y * WW + xg * 4;
        float4 e = *(const float4*)(ep + off);
        float4 d = *(const float4*)(dp + off);
        float4 o;
        o.x = d.x + A0 * e.x + B0v;
        o.y = d.y + A1 * e.y + B1v;
        o.z = d.z + A2 * e.z + B2;
        o.w = d.w + A3 * e.w + B3;
        *(float4*)(op + off) = o;
    }
}

extern "C" void kernel_launch(void* const* d_in, const int* in_sizes, int n_in,
                              void* d_out, int out_size) {
    const float* F_enc = (const float*)d_in[0];
    const float* F_dec = (const float*)d_in[1];
    const float* w_rg  = (const float*)d_in[2];
    const float* w_rt  = (const float*)d_in[3];
    const float* w_ua  = (const float*)d_in[4];
    const float* w_ub  = (const float*)d_in[5];
    const float* eps   = (const float*)d_in[6];
    float* out = (float*)d_out;

    k_prep<<<64, 256>>>(w_rg, w_rt, w_ua, w_ub);
    k_ds_proj<<<dim3(64, 2, 2), 256>>>(F_enc, F_dec);
    k_guided<<<BB*RR, 256>>>(eps);
    k_proj_rc<<<dim3(32, 16), 256>>>();
    k_fuse<<<BB*CC, 256>>>(F_enc, F_dec, out);
}